// round 10
// baseline (speedup 1.0000x reference)
#include <cuda_runtime.h>

#define BATCH  4
#define CCH    64
#define NPIX   16384
#define NHEADS 8
#define DHEAD  64
#define INNER  512
#define EPSN   1e-12f

typedef unsigned long long ull;

__device__ __forceinline__ ull splat2(float a) {
    unsigned u = __float_as_uint(a);
    ull r; asm("mov.b64 %0, {%1, %1};" : "=l"(r) : "r"(u)); return r;
}
__device__ __forceinline__ void fma2(ull& d, ull a, ull b) {
    asm("fma.rn.f32x2 %0, %1, %2, %0;" : "+l"(d) : "l"(a), "l"(b));
}
__device__ __forceinline__ float2 unpk(ull v) {
    unsigned lo, hi; asm("mov.b64 {%0, %1}, %2;" : "=r"(lo), "=r"(hi) : "l"(v));
    return make_float2(__uint_as_float(lo), __uint_as_float(hi));
}
__device__ __forceinline__ void cp16(float* s, const float* g) {
    unsigned sa = (unsigned)__cvta_generic_to_shared(s);
    asm volatile("cp.async.cg.shared.global [%0], [%1], 16;" :: "r"(sa), "l"(g));
}
#define CP_COMMIT()  asm volatile("cp.async.commit_group;")
#define CP_WAIT(N)   asm volatile("cp.async.wait_group %0;" :: "n"(N))

// ---------------- scratch ------------------------------------------------------
__device__ float    g_G[BATCH * CCH * CCH];   // zeroed at load; re-zeroed by attn
__device__ float    g_P[BATCH * CCH * CCH];   // zeroed at load; re-zeroed by out
__device__ unsigned g_cntG[BATCH];
__device__ unsigned g_cntP[BATCH];

// ---------------- K1: Gram, cp.async double-buffered 64px subchunks -----------
#define GSUB 64
#define XS   68

__global__ void __launch_bounds__(256)
gram_kernel(const float* __restrict__ x) {
    __shared__ float xs[2][CCH * XS];         // 2 x 17.4KB
    const int b   = blockIdx.x >> 7;
    const int blk = blockIdx.x & 127;
    const int n0  = blk * 128;                // this block covers 128 pixels
    const int tid = threadIdx.x;

    const float* xb = x + (size_t)b * CCH * NPIX + n0;

    // stage subchunk 0 (group depth 1 after this commit)
    for (int i = tid; i < CCH * (GSUB / 4); i += 256) {
        int c = i >> 4, q = i & 15;
        cp16(&xs[0][c * XS + q * 4], xb + (size_t)c * NPIX + q * 4);
    }
    CP_COMMIT();
    // stage subchunk 1
    for (int i = tid; i < CCH * (GSUB / 4); i += 256) {
        int c = i >> 4, q = i & 15;
        cp16(&xs[1][c * XS + q * 4], xb + (size_t)c * NPIX + GSUB + q * 4);
    }
    CP_COMMIT();

    const int ti = tid >> 4;                  // rows ti + 16u
    const int tj = tid & 15;                  // cols tj + 16v

    ull acc[4][4];
    #pragma unroll
    for (int u = 0; u < 4; u++)
        #pragma unroll
        for (int v = 0; v < 4; v++) acc[u][v] = 0ull;

    #pragma unroll
    for (int s = 0; s < 2; s++) {
        if (s == 0) { CP_WAIT(1); } else { CP_WAIT(0); }
        __syncthreads();
        const float* buf = xs[s];
        #pragma unroll 2
        for (int n = 0; n < GSUB; n += 4) {
            ulonglong2 a[4], bb[4];
            #pragma unroll
            for (int u = 0; u < 4; u++) a[u]  = *(const ulonglong2*)&buf[(ti + 16 * u) * XS + n];
            #pragma unroll
            for (int v = 0; v < 4; v++) bb[v] = *(const ulonglong2*)&buf[(tj + 16 * v) * XS + n];
            #pragma unroll
            for (int u = 0; u < 4; u++) {
                fma2(acc[u][0], a[u].x, bb[0].x); fma2(acc[u][1], a[u].x, bb[1].x);
                fma2(acc[u][2], a[u].x, bb[2].x); fma2(acc[u][3], a[u].x, bb[3].x);
                fma2(acc[u][0], a[u].y, bb[0].y); fma2(acc[u][1], a[u].y, bb[1].y);
                fma2(acc[u][2], a[u].y, bb[2].y); fma2(acc[u][3], a[u].y, bb[3].y);
            }
        }
    }

    float* Gb = g_G + b * CCH * CCH;
    #pragma unroll
    for (int u = 0; u < 4; u++)
        #pragma unroll
        for (int v = 0; v < 4; v++) {
            float2 p = unpk(acc[u][v]);
            atomicAdd(&Gb[(ti + 16 * u) * CCH + (tj + 16 * v)], p.x + p.y);
        }
}

// ---------------- K2: attention in channel space (R6 version) -----------------
#define S68 68
#define OFF_G    0
#define OFF_WQ   (OFF_G  + CCH * 65)
#define OFF_WK   (OFF_WQ + CCH * CCH)
#define OFF_T1   (OFF_WK + CCH * CCH)
#define OFF_T2   (OFF_T1 + CCH * S68)
#define OFF_A    (OFF_T2 + CCH * S68)
#define OFF_WP   (OFF_A  + CCH * S68)
#define OFF_WVT  (OFF_WP + CCH * CCH)
#define OFF_QN   (OFF_WVT + CCH * S68)
#define OFF_KN   (OFF_QN + CCH)
#define ATTN_SMEM ((OFF_KN + CCH) * 4)

__global__ void __launch_bounds__(256)
attn_kernel(const float* __restrict__ Wq,
            const float* __restrict__ Wk,
            const float* __restrict__ Wv,
            const float* __restrict__ Wp,
            const float* __restrict__ rescale,
            float* __restrict__ attn_out) {
    extern __shared__ float sm[];
    float* Gs  = sm + OFF_G;
    float* Wqs = sm + OFF_WQ;
    float* Wks = sm + OFF_WK;
    float* T1  = sm + OFF_T1;
    float* T2  = sm + OFF_T2;
    float* As  = sm + OFF_A;
    float* Wps = sm + OFF_WP;
    float* WvT = sm + OFF_WVT;
    float* qn  = sm + OFF_QN;
    float* kn  = sm + OFF_KN;
    __shared__ int s_last;

    const int b   = blockIdx.x >> 3;
    const int h   = blockIdx.x & 7;
    const int tid = threadIdx.x;
    const int ti  = tid >> 4, tj = tid & 15;
    const int r0  = ti * 4,   e0 = tj * 4;

    for (int i = tid; i < CCH * CCH; i += 256) {
        int r = i >> 6, c = i & 63;
        Gs[r * 65 + c] = g_G[b * CCH * CCH + i];
        Wqs[i] = Wq[r * INNER + h * DHEAD + c];
        Wks[i] = Wk[r * INNER + h * DHEAD + c];
    }
    __syncthreads();
    if (tid == 0) s_last = (atomicAdd(&g_cntG[b], 1u) == NHEADS - 1) ? 1 : 0;

    // T1 = G @ Wq, T2 = G @ Wk
    {
        ull aq[4][2], ak[4][2];
        #pragma unroll
        for (int u = 0; u < 4; u++) { aq[u][0]=aq[u][1]=ak[u][0]=ak[u][1]=0ull; }

        for (int c = 0; c < CCH; c++) {
            float a0 = Gs[(r0 + 0) * 65 + c], a1 = Gs[(r0 + 1) * 65 + c];
            float a2 = Gs[(r0 + 2) * 65 + c], a3 = Gs[(r0 + 3) * 65 + c];
            ulonglong2 bq = *(const ulonglong2*)&Wqs[c * CCH + e0];
            ulonglong2 bk = *(const ulonglong2*)&Wks[c * CCH + e0];
            ull s0 = splat2(a0), s1 = splat2(a1), s2 = splat2(a2), s3 = splat2(a3);
            fma2(aq[0][0], s0, bq.x); fma2(aq[0][1], s0, bq.y);
            fma2(aq[1][0], s1, bq.x); fma2(aq[1][1], s1, bq.y);
            fma2(aq[2][0], s2, bq.x); fma2(aq[2][1], s2, bq.y);
            fma2(aq[3][0], s3, bq.x); fma2(aq[3][1], s3, bq.y);
            fma2(ak[0][0], s0, bk.x); fma2(ak[0][1], s0, bk.y);
            fma2(ak[1][0], s1, bk.x); fma2(ak[1][1], s1, bk.y);
            fma2(ak[2][0], s2, bk.x); fma2(ak[2][1], s2, bk.y);
            fma2(ak[3][0], s3, bk.x); fma2(ak[3][1], s3, bk.y);
        }
        #pragma unroll
        for (int u = 0; u < 4; u++) {
            float2 q0 = unpk(aq[u][0]), q1 = unpk(aq[u][1]);
            float2 k0 = unpk(ak[u][0]), k1 = unpk(ak[u][1]);
            *(float4*)&T1[(r0 + u) * S68 + e0] = make_float4(q0.x, q0.y, q1.x, q1.y);
            *(float4*)&T2[(r0 + u) * S68 + e0] = make_float4(k0.x, k0.y, k1.x, k1.y);
        }
    }
    __syncthreads();

    if (tid < 128) {
        const int e = tid & 63;
        const float* W = (tid < 64) ? Wqs : Wks;
        const float* T = (tid < 64) ? T1  : T2;
        float s = 0.f;
        #pragma unroll 8
        for (int c = 0; c < CCH; c++) s = fmaf(W[c * CCH + e], T[c * S68 + e], s);
        ((tid < 64) ? qn : kn)[e] = 1.f / fmaxf(sqrtf(s), EPSN);
    }

    // A_raw = T2^T @ Wq
    {
        ull acc[4][2];
        #pragma unroll
        for (int u = 0; u < 4; u++) { acc[u][0] = acc[u][1] = 0ull; }
        for (int c = 0; c < CCH; c++) {
            float4 av = *(const float4*)&T2[c * S68 + r0];
            ulonglong2 bv = *(const ulonglong2*)&Wqs[c * CCH + e0];
            ull s0 = splat2(av.x), s1 = splat2(av.y), s2 = splat2(av.z), s3 = splat2(av.w);
            fma2(acc[0][0], s0, bv.x); fma2(acc[0][1], s0, bv.y);
            fma2(acc[1][0], s1, bv.x); fma2(acc[1][1], s1, bv.y);
            fma2(acc[2][0], s2, bv.x); fma2(acc[2][1], s2, bv.y);
            fma2(acc[3][0], s3, bv.x); fma2(acc[3][1], s3, bv.y);
        }
        #pragma unroll
        for (int u = 0; u < 4; u++) {
            float2 p0 = unpk(acc[u][0]), p1 = unpk(acc[u][1]);
            *(float4*)&As[(r0 + u) * S68 + e0] = make_float4(p0.x, p0.y, p1.x, p1.y);
        }
    }

    for (int i = tid; i < CCH * CCH; i += 256) {
        int r = i >> 6, c = i & 63;
        Wps[i] = Wp[(h * DHEAD + r) * CCH + c];
        WvT[c * S68 + r] = Wv[r * INNER + h * DHEAD + c];
    }
    __syncthreads();

    // scaled softmax (4 lanes per row)
    {
        const int d = tid >> 2, g = tid & 3;
        float* row = As + d * S68;
        const float sk = kn[d] * rescale[h];
        float vals[16];
        float mx = -1e30f;
        #pragma unroll
        for (int k = 0; k < 16; k++) {
            int e = g + 4 * k;
            float v = row[e] * sk * qn[e];
            vals[k] = v;
            mx = fmaxf(mx, v);
        }
        mx = fmaxf(mx, __shfl_xor_sync(0xffffffffu, mx, 1));
        mx = fmaxf(mx, __shfl_xor_sync(0xffffffffu, mx, 2));
        float s = 0.f;
        #pragma unroll
        for (int k = 0; k < 16; k++) { vals[k] = __expf(vals[k] - mx); s += vals[k]; }
        s += __shfl_xor_sync(0xffffffffu, s, 1);
        s += __shfl_xor_sync(0xffffffffu, s, 2);
        float inv = 1.f / s;
        #pragma unroll
        for (int k = 0; k < 16; k++) row[g + 4 * k] = vals[k] * inv;
    }
    __syncthreads();

    float* ao = attn_out + (size_t)(b * NHEADS + h) * DHEAD * DHEAD;
    for (int i = tid; i < CCH * CCH; i += 256)
        ao[i] = As[(i >> 6) * S68 + (i & 63)];

    // M[e][c] = sum_d A[d][e] * Wp[d][c]  -> T1
    {
        ull acc[4][2];
        #pragma unroll
        for (int u = 0; u < 4; u++) { acc[u][0] = acc[u][1] = 0ull; }
        for (int d = 0; d < CCH; d++) {
            float4 av = *(const float4*)&As[d * S68 + r0];
            ulonglong2 bv = *(const ulonglong2*)&Wps[d * CCH + e0];
            ull s0 = splat2(av.x), s1 = splat2(av.y), s2 = splat2(av.z), s3 = splat2(av.w);
            fma2(acc[0][0], s0, bv.x); fma2(acc[0][1], s0, bv.y);
            fma2(acc[1][0], s1, bv.x); fma2(acc[1][1], s1, bv.y);
            fma2(acc[2][0], s2, bv.x); fma2(acc[2][1], s2, bv.y);
            fma2(acc[3][0], s3, bv.x); fma2(acc[3][1], s3, bv.y);
        }
        #pragma unroll
        for (int u = 0; u < 4; u++) {
            float2 p0 = unpk(acc[u][0]), p1 = unpk(acc[u][1]);
            *(float4*)&T1[(r0 + u) * S68 + e0] = make_float4(p0.x, p0.y, p1.x, p1.y);
        }
    }
    __syncthreads();

    // P[cin][c] += Wv[cin][:] @ M[:][c]
    {
        ull acc[4][2];
        #pragma unroll
        for (int u = 0; u < 4; u++) { acc[u][0] = acc[u][1] = 0ull; }
        for (int e = 0; e < CCH; e++) {
            float4 av = *(const float4*)&WvT[e * S68 + r0];
            ulonglong2 bv = *(const ulonglong2*)&T1[e * S68 + e0];
            ull s0 = splat2(av.x), s1 = splat2(av.y), s2 = splat2(av.z), s3 = splat2(av.w);
            fma2(acc[0][0], s0, bv.x); fma2(acc[0][1], s0, bv.y);
            fma2(acc[1][0], s1, bv.x); fma2(acc[1][1], s1, bv.y);
            fma2(acc[2][0], s2, bv.x); fma2(acc[2][1], s2, bv.y);
            fma2(acc[3][0], s3, bv.x); fma2(acc[3][1], s3, bv.y);
        }
        float* Pb = g_P + b * CCH * CCH;
        #pragma unroll
        for (int u = 0; u < 4; u++) {
            float2 p0 = unpk(acc[u][0]), p1 = unpk(acc[u][1]);
            atomicAdd(&Pb[(r0 + u) * CCH + e0 + 0], p0.x);
            atomicAdd(&Pb[(r0 + u) * CCH + e0 + 1], p0.y);
            atomicAdd(&Pb[(r0 + u) * CCH + e0 + 2], p1.x);
            atomicAdd(&Pb[(r0 + u) * CCH + e0 + 3], p1.y);
        }
    }

    __syncthreads();
    if (s_last) {
        for (int i = tid; i < CCH * CCH; i += 256) g_G[b * CCH * CCH + i] = 0.f;
        if (tid == 0) g_cntG[b] = 0u;
    }
}

// ---------------- K3: out = X @ P + bp, cp.async double-buffered --------------
#define OSUB 64
#define OXS  68
#define OFF_X0  0
#define OFF_X1  (CCH * OXS)
#define OFF_PS  (2 * CCH * OXS)
#define OFF_BP  (OFF_PS + CCH * CCH)
#define OUT_SMEM ((OFF_BP + CCH) * 4)

__global__ void __launch_bounds__(256)
out_kernel(const float* __restrict__ x,
           const float* __restrict__ bp,
           float* __restrict__ out) {
    extern __shared__ float sm[];
    float* xs0 = sm + OFF_X0;
    float* xs1 = sm + OFF_X1;
    float* Ps  = sm + OFF_PS;
    float* bps = sm + OFF_BP;
    __shared__ int s_last;

    const int b   = blockIdx.x >> 7;
    const int blk = blockIdx.x & 127;
    const int n0  = blk * 128;
    const int tid = threadIdx.x;

    const float* xb = x + (size_t)b * CCH * NPIX + n0;
    const float* Pg = g_P + b * CCH * CCH;

    // group 0: Ps + x sub0
    for (int i = tid; i < CCH * CCH / 4; i += 256) cp16(&Ps[i * 4], Pg + i * 4);
    for (int i = tid; i < CCH * (OSUB / 4); i += 256) {
        int c = i >> 4, q = i & 15;
        cp16(&xs0[c * OXS + q * 4], xb + (size_t)c * NPIX + q * 4);
    }
    CP_COMMIT();
    // group 1: x sub1
    for (int i = tid; i < CCH * (OSUB / 4); i += 256) {
        int c = i >> 4, q = i & 15;
        cp16(&xs1[c * OXS + q * 4], xb + (size_t)c * NPIX + OSUB + q * 4);
    }
    CP_COMMIT();
    if (tid < CCH) bps[tid] = bp[tid];
    if (tid == 0) s_last = (atomicAdd(&g_cntP[b], 1u) == 127u) ? 1 : 0;

    const int tx = tid & 15;                  // pixels tx*4..+3 (within subtile)
    const int ty = tid >> 4;                  // channels ty*4..+3
    const int c0 = ty * 4;

    #pragma unroll
    for (int s = 0; s < 2; s++) {
        if (s == 0) { CP_WAIT(1); } else { CP_WAIT(0); }
        __syncthreads();
        const float* buf = (s == 0) ? xs0 : xs1;

        ull acc[4][2];
        #pragma unroll
        for (int u = 0; u < 4; u++) { acc[u][0] = acc[u][1] = 0ull; }

        #pragma unroll 4
        for (int j = 0; j < CCH; j++) {
            ulonglong2 xv = *(const ulonglong2*)&buf[j * OXS + tx * 4];
            float4 p = *(const float4*)&Ps[j * CCH + c0];
            ull s0 = splat2(p.x), s1 = splat2(p.y), s2 = splat2(p.z), s3 = splat2(p.w);
            fma2(acc[0][0], s0, xv.x); fma2(acc[0][1], s0, xv.y);
            fma2(acc[1][0], s1, xv.x); fma2(acc[1][1], s1, xv.y);
            fma2(acc[2][0], s2, xv.x); fma2(acc[2][1], s2, xv.y);
            fma2(acc[3][0], s3, xv.x); fma2(acc[3][1], s3, xv.y);
        }

        const int nb = n0 + s * OSUB;
        #pragma unroll
        for (int u = 0; u < 4; u++) {
            float bias = bps[c0 + u];
            float2 f0 = unpk(acc[u][0]), f1 = unpk(acc[u][1]);
            *(float4*)(out + ((size_t)(b * CCH + c0 + u)) * NPIX + nb + tx * 4) =
                make_float4(f0.x + bias, f0.y + bias, f1.x + bias, f1.y + bias);
        }
    }

    __syncthreads();
    if (s_last) {
        for (int i = tid; i < CCH * CCH; i += 256) g_P[b * CCH * CCH + i] = 0.f;
        if (tid == 0) g_cntP[b] = 0u;
    }
}

// ---------------- launch ------------------------------------------------------
extern "C" void kernel_launch(void* const* d_in, const int* in_sizes, int n_in,
                              void* d_out, int out_size) {
    const float* x       = (const float*)d_in[0];
    const float* Wq      = (const float*)d_in[1];
    const float* Wk      = (const float*)d_in[2];
    const float* Wv      = (const float*)d_in[3];
    const float* Wp      = (const float*)d_in[4];
    const float* bp      = (const float*)d_in[5];
    const float* rescale = (const float*)d_in[6];

    float* out      = (float*)d_out;
    float* attn_out = out + (size_t)out_size - (size_t)BATCH * NHEADS * DHEAD * DHEAD;

    cudaFuncSetAttribute(attn_kernel, cudaFuncAttributeMaxDynamicSharedMemorySize, ATTN_SMEM);
    cudaFuncSetAttribute(out_kernel,  cudaFuncAttributeMaxDynamicSharedMemorySize, OUT_SMEM);

    gram_kernel<<<BATCH * 128, 256>>>(x);
    attn_kernel<<<BATCH * NHEADS, 256, ATTN_SMEM>>>(Wq, Wk, Wv, Wp, rescale, attn_out);
    out_kernel<<<BATCH * 128, 256, OUT_SMEM>>>(x, bp, out);
}

// round 11
// speedup vs baseline: 1.0746x; 1.0746x over previous
#include <cuda_runtime.h>

#define BATCH  4
#define CCH    64
#define NPIX   16384
#define NHEADS 8
#define DHEAD  64
#define INNER  512
#define EPSN   1e-12f

typedef unsigned long long ull;

__device__ __forceinline__ ull splat2(float a) {
    unsigned u = __float_as_uint(a);
    ull r; asm("mov.b64 %0, {%1, %1};" : "=l"(r) : "r"(u)); return r;
}
__device__ __forceinline__ void fma2(ull& d, ull a, ull b) {
    asm("fma.rn.f32x2 %0, %1, %2, %0;" : "+l"(d) : "l"(a), "l"(b));
}
__device__ __forceinline__ float2 unpk(ull v) {
    unsigned lo, hi; asm("mov.b64 {%0, %1}, %2;" : "=r"(lo), "=r"(hi) : "l"(v));
    return make_float2(__uint_as_float(lo), __uint_as_float(hi));
}
__device__ __forceinline__ void cp16(float* s, const float* g) {
    unsigned sa = (unsigned)__cvta_generic_to_shared(s);
    asm volatile("cp.async.cg.shared.global [%0], [%1], 16;" :: "r"(sa), "l"(g));
}
#define CP_COMMIT()  asm volatile("cp.async.commit_group;")
#define CP_WAIT(N)   asm volatile("cp.async.wait_group %0;" :: "n"(N))

// ---------------- scratch ------------------------------------------------------
__device__ float    g_G[BATCH * CCH * CCH];   // zeroed at load; re-zeroed by attn
__device__ float    g_P[BATCH * CCH * CCH];   // zeroed at load; re-zeroed by out
__device__ unsigned g_cntG[BATCH];
__device__ unsigned g_cntP[BATCH];

// ---------------- K1: Gram, cp.async double-buffered (R9 version) -------------
#define GSUB 64
#define XS   68

__global__ void __launch_bounds__(256)
gram_kernel(const float* __restrict__ x) {
    __shared__ float xs[2][CCH * XS];         // 2 x 17.4KB
    const int b   = blockIdx.x >> 7;
    const int blk = blockIdx.x & 127;
    const int n0  = blk * 128;
    const int tid = threadIdx.x;

    const float* xb = x + (size_t)b * CCH * NPIX + n0;

    for (int i = tid; i < CCH * (GSUB / 4); i += 256) {
        int c = i >> 4, q = i & 15;
        cp16(&xs[0][c * XS + q * 4], xb + (size_t)c * NPIX + q * 4);
    }
    CP_COMMIT();
    for (int i = tid; i < CCH * (GSUB / 4); i += 256) {
        int c = i >> 4, q = i & 15;
        cp16(&xs[1][c * XS + q * 4], xb + (size_t)c * NPIX + GSUB + q * 4);
    }
    CP_COMMIT();

    const int ti = tid >> 4;                  // rows ti + 16u
    const int tj = tid & 15;                  // cols tj + 16v

    ull acc[4][4];
    #pragma unroll
    for (int u = 0; u < 4; u++)
        #pragma unroll
        for (int v = 0; v < 4; v++) acc[u][v] = 0ull;

    #pragma unroll
    for (int s = 0; s < 2; s++) {
        if (s == 0) { CP_WAIT(1); } else { CP_WAIT(0); }
        __syncthreads();
        const float* buf = xs[s];
        #pragma unroll 2
        for (int n = 0; n < GSUB; n += 4) {
            ulonglong2 a[4], bb[4];
            #pragma unroll
            for (int u = 0; u < 4; u++) a[u]  = *(const ulonglong2*)&buf[(ti + 16 * u) * XS + n];
            #pragma unroll
            for (int v = 0; v < 4; v++) bb[v] = *(const ulonglong2*)&buf[(tj + 16 * v) * XS + n];
            #pragma unroll
            for (int u = 0; u < 4; u++) {
                fma2(acc[u][0], a[u].x, bb[0].x); fma2(acc[u][1], a[u].x, bb[1].x);
                fma2(acc[u][2], a[u].x, bb[2].x); fma2(acc[u][3], a[u].x, bb[3].x);
                fma2(acc[u][0], a[u].y, bb[0].y); fma2(acc[u][1], a[u].y, bb[1].y);
                fma2(acc[u][2], a[u].y, bb[2].y); fma2(acc[u][3], a[u].y, bb[3].y);
            }
        }
    }

    float* Gb = g_G + b * CCH * CCH;
    #pragma unroll
    for (int u = 0; u < 4; u++)
        #pragma unroll
        for (int v = 0; v < 4; v++) {
            float2 p = unpk(acc[u][v]);
            atomicAdd(&Gb[(ti + 16 * u) * CCH + (tj + 16 * v)], p.x + p.y);
        }
}

// ---------------- K2: attention in channel space (R6 version) -----------------
#define S68 68
#define OFF_G    0
#define OFF_WQ   (OFF_G  + CCH * 65)
#define OFF_WK   (OFF_WQ + CCH * CCH)
#define OFF_T1   (OFF_WK + CCH * CCH)
#define OFF_T2   (OFF_T1 + CCH * S68)
#define OFF_A    (OFF_T2 + CCH * S68)
#define OFF_WP   (OFF_A  + CCH * S68)
#define OFF_WVT  (OFF_WP + CCH * CCH)
#define OFF_QN   (OFF_WVT + CCH * S68)
#define OFF_KN   (OFF_QN + CCH)
#define ATTN_SMEM ((OFF_KN + CCH) * 4)

__global__ void __launch_bounds__(256)
attn_kernel(const float* __restrict__ Wq,
            const float* __restrict__ Wk,
            const float* __restrict__ Wv,
            const float* __restrict__ Wp,
            const float* __restrict__ rescale,
            float* __restrict__ attn_out) {
    extern __shared__ float sm[];
    float* Gs  = sm + OFF_G;
    float* Wqs = sm + OFF_WQ;
    float* Wks = sm + OFF_WK;
    float* T1  = sm + OFF_T1;
    float* T2  = sm + OFF_T2;
    float* As  = sm + OFF_A;
    float* Wps = sm + OFF_WP;
    float* WvT = sm + OFF_WVT;
    float* qn  = sm + OFF_QN;
    float* kn  = sm + OFF_KN;
    __shared__ int s_last;

    const int b   = blockIdx.x >> 3;
    const int h   = blockIdx.x & 7;
    const int tid = threadIdx.x;
    const int ti  = tid >> 4, tj = tid & 15;
    const int r0  = ti * 4,   e0 = tj * 4;

    for (int i = tid; i < CCH * CCH; i += 256) {
        int r = i >> 6, c = i & 63;
        Gs[r * 65 + c] = g_G[b * CCH * CCH + i];
        Wqs[i] = Wq[r * INNER + h * DHEAD + c];
        Wks[i] = Wk[r * INNER + h * DHEAD + c];
    }
    __syncthreads();
    if (tid == 0) s_last = (atomicAdd(&g_cntG[b], 1u) == NHEADS - 1) ? 1 : 0;

    // T1 = G @ Wq, T2 = G @ Wk
    {
        ull aq[4][2], ak[4][2];
        #pragma unroll
        for (int u = 0; u < 4; u++) { aq[u][0]=aq[u][1]=ak[u][0]=ak[u][1]=0ull; }

        for (int c = 0; c < CCH; c++) {
            float a0 = Gs[(r0 + 0) * 65 + c], a1 = Gs[(r0 + 1) * 65 + c];
            float a2 = Gs[(r0 + 2) * 65 + c], a3 = Gs[(r0 + 3) * 65 + c];
            ulonglong2 bq = *(const ulonglong2*)&Wqs[c * CCH + e0];
            ulonglong2 bk = *(const ulonglong2*)&Wks[c * CCH + e0];
            ull s0 = splat2(a0), s1 = splat2(a1), s2 = splat2(a2), s3 = splat2(a3);
            fma2(aq[0][0], s0, bq.x); fma2(aq[0][1], s0, bq.y);
            fma2(aq[1][0], s1, bq.x); fma2(aq[1][1], s1, bq.y);
            fma2(aq[2][0], s2, bq.x); fma2(aq[2][1], s2, bq.y);
            fma2(aq[3][0], s3, bq.x); fma2(aq[3][1], s3, bq.y);
            fma2(ak[0][0], s0, bk.x); fma2(ak[0][1], s0, bk.y);
            fma2(ak[1][0], s1, bk.x); fma2(ak[1][1], s1, bk.y);
            fma2(ak[2][0], s2, bk.x); fma2(ak[2][1], s2, bk.y);
            fma2(ak[3][0], s3, bk.x); fma2(ak[3][1], s3, bk.y);
        }
        #pragma unroll
        for (int u = 0; u < 4; u++) {
            float2 q0 = unpk(aq[u][0]), q1 = unpk(aq[u][1]);
            float2 k0 = unpk(ak[u][0]), k1 = unpk(ak[u][1]);
            *(float4*)&T1[(r0 + u) * S68 + e0] = make_float4(q0.x, q0.y, q1.x, q1.y);
            *(float4*)&T2[(r0 + u) * S68 + e0] = make_float4(k0.x, k0.y, k1.x, k1.y);
        }
    }
    __syncthreads();

    if (tid < 128) {
        const int e = tid & 63;
        const float* W = (tid < 64) ? Wqs : Wks;
        const float* T = (tid < 64) ? T1  : T2;
        float s = 0.f;
        #pragma unroll 8
        for (int c = 0; c < CCH; c++) s = fmaf(W[c * CCH + e], T[c * S68 + e], s);
        ((tid < 64) ? qn : kn)[e] = 1.f / fmaxf(sqrtf(s), EPSN);
    }

    // A_raw = T2^T @ Wq
    {
        ull acc[4][2];
        #pragma unroll
        for (int u = 0; u < 4; u++) { acc[u][0] = acc[u][1] = 0ull; }
        for (int c = 0; c < CCH; c++) {
            float4 av = *(const float4*)&T2[c * S68 + r0];
            ulonglong2 bv = *(const ulonglong2*)&Wqs[c * CCH + e0];
            ull s0 = splat2(av.x), s1 = splat2(av.y), s2 = splat2(av.z), s3 = splat2(av.w);
            fma2(acc[0][0], s0, bv.x); fma2(acc[0][1], s0, bv.y);
            fma2(acc[1][0], s1, bv.x); fma2(acc[1][1], s1, bv.y);
            fma2(acc[2][0], s2, bv.x); fma2(acc[2][1], s2, bv.y);
            fma2(acc[3][0], s3, bv.x); fma2(acc[3][1], s3, bv.y);
        }
        #pragma unroll
        for (int u = 0; u < 4; u++) {
            float2 p0 = unpk(acc[u][0]), p1 = unpk(acc[u][1]);
            *(float4*)&As[(r0 + u) * S68 + e0] = make_float4(p0.x, p0.y, p1.x, p1.y);
        }
    }

    for (int i = tid; i < CCH * CCH; i += 256) {
        int r = i >> 6, c = i & 63;
        Wps[i] = Wp[(h * DHEAD + r) * CCH + c];
        WvT[c * S68 + r] = Wv[r * INNER + h * DHEAD + c];
    }
    __syncthreads();

    // scaled softmax (4 lanes per row)
    {
        const int d = tid >> 2, g = tid & 3;
        float* row = As + d * S68;
        const float sk = kn[d] * rescale[h];
        float vals[16];
        float mx = -1e30f;
        #pragma unroll
        for (int k = 0; k < 16; k++) {
            int e = g + 4 * k;
            float v = row[e] * sk * qn[e];
            vals[k] = v;
            mx = fmaxf(mx, v);
        }
        mx = fmaxf(mx, __shfl_xor_sync(0xffffffffu, mx, 1));
        mx = fmaxf(mx, __shfl_xor_sync(0xffffffffu, mx, 2));
        float s = 0.f;
        #pragma unroll
        for (int k = 0; k < 16; k++) { vals[k] = __expf(vals[k] - mx); s += vals[k]; }
        s += __shfl_xor_sync(0xffffffffu, s, 1);
        s += __shfl_xor_sync(0xffffffffu, s, 2);
        float inv = 1.f / s;
        #pragma unroll
        for (int k = 0; k < 16; k++) row[g + 4 * k] = vals[k] * inv;
    }
    __syncthreads();

    float* ao = attn_out + (size_t)(b * NHEADS + h) * DHEAD * DHEAD;
    for (int i = tid; i < CCH * CCH; i += 256)
        ao[i] = As[(i >> 6) * S68 + (i & 63)];

    // M[e][c] = sum_d A[d][e] * Wp[d][c]  -> T1
    {
        ull acc[4][2];
        #pragma unroll
        for (int u = 0; u < 4; u++) { acc[u][0] = acc[u][1] = 0ull; }
        for (int d = 0; d < CCH; d++) {
            float4 av = *(const float4*)&As[d * S68 + r0];
            ulonglong2 bv = *(const ulonglong2*)&Wps[d * CCH + e0];
            ull s0 = splat2(av.x), s1 = splat2(av.y), s2 = splat2(av.z), s3 = splat2(av.w);
            fma2(acc[0][0], s0, bv.x); fma2(acc[0][1], s0, bv.y);
            fma2(acc[1][0], s1, bv.x); fma2(acc[1][1], s1, bv.y);
            fma2(acc[2][0], s2, bv.x); fma2(acc[2][1], s2, bv.y);
            fma2(acc[3][0], s3, bv.x); fma2(acc[3][1], s3, bv.y);
        }
        #pragma unroll
        for (int u = 0; u < 4; u++) {
            float2 p0 = unpk(acc[u][0]), p1 = unpk(acc[u][1]);
            *(float4*)&T1[(r0 + u) * S68 + e0] = make_float4(p0.x, p0.y, p1.x, p1.y);
        }
    }
    __syncthreads();

    // P[cin][c] += Wv[cin][:] @ M[:][c]
    {
        ull acc[4][2];
        #pragma unroll
        for (int u = 0; u < 4; u++) { acc[u][0] = acc[u][1] = 0ull; }
        for (int e = 0; e < CCH; e++) {
            float4 av = *(const float4*)&WvT[e * S68 + r0];
            ulonglong2 bv = *(const ulonglong2*)&T1[e * S68 + e0];
            ull s0 = splat2(av.x), s1 = splat2(av.y), s2 = splat2(av.z), s3 = splat2(av.w);
            fma2(acc[0][0], s0, bv.x); fma2(acc[0][1], s0, bv.y);
            fma2(acc[1][0], s1, bv.x); fma2(acc[1][1], s1, bv.y);
            fma2(acc[2][0], s2, bv.x); fma2(acc[2][1], s2, bv.y);
            fma2(acc[3][0], s3, bv.x); fma2(acc[3][1], s3, bv.y);
        }
        float* Pb = g_P + b * CCH * CCH;
        #pragma unroll
        for (int u = 0; u < 4; u++) {
            float2 p0 = unpk(acc[u][0]), p1 = unpk(acc[u][1]);
            atomicAdd(&Pb[(r0 + u) * CCH + e0 + 0], p0.x);
            atomicAdd(&Pb[(r0 + u) * CCH + e0 + 1], p0.y);
            atomicAdd(&Pb[(r0 + u) * CCH + e0 + 2], p1.x);
            atomicAdd(&Pb[(r0 + u) * CCH + e0 + 3], p1.y);
        }
    }

    __syncthreads();
    if (s_last) {
        for (int i = tid; i < CCH * CCH; i += 256) g_G[b * CCH * CCH + i] = 0.f;
        if (tid == 0) g_cntG[b] = 0u;
    }
}

// ---------------- K3: out = X @ P + bp (R6 version: 8ch x 4px, ONTILE 128) ----
#define ONTILE 128
#define X2S    132
#define OUT_SMEM ((CCH * X2S + CCH * CCH + CCH) * 4)

__global__ void __launch_bounds__(256)
out_kernel(const float* __restrict__ x,
           const float* __restrict__ bp,
           float* __restrict__ out) {
    extern __shared__ float sm[];
    float* xs  = sm;                           // [64][132]
    float* Ps  = xs + CCH * X2S;               // [64][64]
    float* bps = Ps + CCH * CCH;
    __shared__ int s_last;

    const int b     = blockIdx.x >> 7;
    const int chunk = blockIdx.x & 127;
    const int n0    = chunk * ONTILE;
    const int tid   = threadIdx.x;

    const float4* Pg = (const float4*)(g_P + b * CCH * CCH);
    for (int i = tid; i < CCH * CCH / 4; i += 256) ((float4*)Ps)[i] = Pg[i];
    if (tid < CCH) bps[tid] = bp[tid];

    const float* xb = x + (size_t)b * CCH * NPIX + n0;
    for (int i = tid; i < CCH * (ONTILE / 4); i += 256) {
        int c = i >> 5, q = i & 31;
        float4 v = *(const float4*)(xb + (size_t)c * NPIX + q * 4);
        *(float4*)(xs + c * X2S + q * 4) = v;
    }
    __syncthreads();
    if (tid == 0) s_last = (atomicAdd(&g_cntP[b], 1u) == 127u) ? 1 : 0;

    const int tx = tid & 31;                   // pixels tx*4..+3
    const int ty = tid >> 5;                   // channels ty*8..+7
    const int c0 = ty * 8;

    ull acc[8][2];
    #pragma unroll
    for (int u = 0; u < 8; u++) { acc[u][0] = acc[u][1] = 0ull; }

    #pragma unroll 4
    for (int j = 0; j < CCH; j++) {
        ulonglong2 xv = *(const ulonglong2*)&xs[j * X2S + tx * 4];
        float4 p0 = *(const float4*)&Ps[j * CCH + c0];
        float4 p1 = *(const float4*)&Ps[j * CCH + c0 + 4];
        float pr[8] = {p0.x, p0.y, p0.z, p0.w, p1.x, p1.y, p1.z, p1.w};
        #pragma unroll
        for (int u = 0; u < 8; u++) {
            ull s = splat2(pr[u]);
            fma2(acc[u][0], s, xv.x); fma2(acc[u][1], s, xv.y);
        }
    }

    #pragma unroll
    for (int u = 0; u < 8; u++) {
        float bias = bps[c0 + u];
        float2 f0 = unpk(acc[u][0]), f1 = unpk(acc[u][1]);
        *(float4*)(out + ((size_t)(b * CCH + c0 + u)) * NPIX + n0 + tx * 4) =
            make_float4(f0.x + bias, f0.y + bias, f1.x + bias, f1.y + bias);
    }

    __syncthreads();
    if (s_last) {
        for (int i = tid; i < CCH * CCH; i += 256) g_P[b * CCH * CCH + i] = 0.f;
        if (tid == 0) g_cntP[b] = 0u;
    }
}

// ---------------- launch ------------------------------------------------------
extern "C" void kernel_launch(void* const* d_in, const int* in_sizes, int n_in,
                              void* d_out, int out_size) {
    const float* x       = (const float*)d_in[0];
    const float* Wq      = (const float*)d_in[1];
    const float* Wk      = (const float*)d_in[2];
    const float* Wv      = (const float*)d_in[3];
    const float* Wp      = (const float*)d_in[4];
    const float* bp      = (const float*)d_in[5];
    const float* rescale = (const float*)d_in[6];

    float* out      = (float*)d_out;
    float* attn_out = out + (size_t)out_size - (size_t)BATCH * NHEADS * DHEAD * DHEAD;

    cudaFuncSetAttribute(attn_kernel, cudaFuncAttributeMaxDynamicSharedMemorySize, ATTN_SMEM);
    cudaFuncSetAttribute(out_kernel,  cudaFuncAttributeMaxDynamicSharedMemorySize, OUT_SMEM);

    gram_kernel<<<BATCH * 128, 256>>>(x);
    attn_kernel<<<BATCH * NHEADS, 256, ATTN_SMEM>>>(Wq, Wk, Wv, Wp, rescale, attn_out);
    out_kernel<<<BATCH * (NPIX / ONTILE), 256, OUT_SMEM>>>(x, bp, out);
}